// round 5
// baseline (speedup 1.0000x reference)
#include <cuda_runtime.h>
#include <math.h>
#include <stdint.h>

#define BATCH 4
#define SEQ   2048
#define DIM   512

// Scratch (__device__ globals — allocation-free per harness rules)
__device__ float g_Xc [BATCH * SEQ * DIM];            // 16 MB  X, tf32-rounded
__device__ float g_QKV[3 * BATCH * SEQ * DIM];        // 48 MB  Q,K,V packed
__device__ float g_Vt [BATCH * SEQ * DIM];            // 16 MB  V^T [b][d][t]
__device__ float g_Wt [3 * DIM * DIM];                // 3 MB   W^T packed
__device__ float g_b3 [3 * DIM];                      // biases packed
__device__ float g_S  [(size_t)BATCH * SEQ * SEQ];    // 64 MB  scores/probs

// ---------------------------------------------------------------------------
__device__ __forceinline__ float to_tf32(float x) {
    float y;
    asm("cvt.rna.tf32.f32 %0, %1;" : "=f"(y) : "f"(x));
    return y;
}

__device__ __forceinline__ void cpa16(float* dst, const float* src)
{
    uint32_t d = (uint32_t)__cvta_generic_to_shared(dst);
    asm volatile("cp.async.cg.shared.global [%0], [%1], 16;" :: "r"(d), "l"(src));
}

// ---------------------------------------------------------------------------
// 3-stage pipelined TF32 mma.sync GEMM: C = alpha * A[MxK] @ B[NxK]^T (+bias)
// A row-major [M][K], B row-major [N][K], inputs tf32-pre-rounded.
// Block tile 128x256x32; 8 warps (2 M x 4 N); warp tile 64x64.
// smem: 3 stages x (A 128x36 + B 256x36) floats = 165888 B. 1 CTA/SM.
// ---------------------------------------------------------------------------
#define ST_F 13824   // floats per stage: 4608 (A) + 9216 (B)

template <bool HAS_BIAS, bool HAS_SCALE, bool CVT_OUT>
__global__ __launch_bounds__(256, 1)
void tf32gemm_big(int M, int N, int K,
                  const float* __restrict__ A, int lda, long long sA,
                  const float* __restrict__ B, int ldb, long long sB,
                  float* __restrict__ C, int ldc, long long sC,
                  float alpha, const float* __restrict__ bias, long long sBias)
{
    extern __shared__ float sm[];

    A += (long long)blockIdx.z * sA;
    B += (long long)blockIdx.z * sB;
    C += (long long)blockIdx.z * sC;
    if (HAS_BIAS) bias += (long long)blockIdx.z * sBias;

    const int tid    = threadIdx.x;
    const int wid    = tid >> 5;
    const int lane   = tid & 31;
    const int gID    = lane >> 2;   // 0..7
    const int tig    = lane & 3;    // 0..3
    const int warp_m = wid & 1;     // 2 warps along M
    const int warp_n = wid >> 1;    // 4 warps along N

    const int bm = blockIdx.y * 128;
    const int bn = blockIdx.x * 256;

    // cp.async mapping: 16B chunks. A tile: 1024 chunks -> 4/thread.
    // B tile: 2048 chunks -> 8/thread.
    const int lrow = tid >> 3;      // 0..31  (+32*i)
    const int lc4  = (tid & 7) * 4; // float offset within 32-float k-row

    const float* Ap = A + (long long)(bm + lrow) * lda + lc4;
    const float* Bp = B + (long long)(bn + lrow) * ldb + lc4;
    const int soff = lrow * 36 + lc4;   // + i*1152 (=32*36)

    const int T = K >> 5;

    // Stage-issue helper (4 A-chunks + 8 B-chunks per thread)
#define ISSUE_STAGE(s, k0)                                                  \
    do {                                                                    \
        float* sa_ = sm + (s) * ST_F;                                       \
        float* sb_ = sa_ + 4608;                                            \
        _Pragma("unroll")                                                   \
        for (int i_ = 0; i_ < 4; i_++)                                      \
            cpa16(sa_ + soff + i_ * 1152,                                   \
                  Ap + (k0) + (long long)i_ * 32 * lda);                    \
        _Pragma("unroll")                                                   \
        for (int i_ = 0; i_ < 8; i_++)                                      \
            cpa16(sb_ + soff + i_ * 1152,                                   \
                  Bp + (k0) + (long long)i_ * 32 * ldb);                    \
    } while (0)

    // Prologue: stages 0 and 1
    ISSUE_STAGE(0, 0);
    asm volatile("cp.async.commit_group;");
    if (T > 1) ISSUE_STAGE(1, 32);
    asm volatile("cp.async.commit_group;");

    float acc[4][8][4];
#pragma unroll
    for (int mi = 0; mi < 4; mi++)
#pragma unroll
        for (int ni = 0; ni < 8; ni++)
#pragma unroll
            for (int t = 0; t < 4; t++) acc[mi][ni][t] = 0.f;

    asm volatile("cp.async.wait_group 1;");
    __syncthreads();

    int s = 0;           // stage being computed
    for (int t = 0; t < T; t++) {
        const float* As = sm + s * ST_F;
        const float* Bs = As + 4608;

#pragma unroll
        for (int kq = 0; kq < 4; kq++) {
            const int kk = kq * 8;
            uint32_t af[4][4], bf[8][2];
#pragma unroll
            for (int mi = 0; mi < 4; mi++) {
                int m = warp_m * 64 + mi * 16 + gID;
                af[mi][0] = __float_as_uint(As[m * 36 + kk + tig]);
                af[mi][1] = __float_as_uint(As[(m + 8) * 36 + kk + tig]);
                af[mi][2] = __float_as_uint(As[m * 36 + kk + tig + 4]);
                af[mi][3] = __float_as_uint(As[(m + 8) * 36 + kk + tig + 4]);
            }
#pragma unroll
            for (int ni = 0; ni < 8; ni++) {
                int n = warp_n * 64 + ni * 8 + gID;
                bf[ni][0] = __float_as_uint(Bs[n * 36 + kk + tig]);
                bf[ni][1] = __float_as_uint(Bs[n * 36 + kk + tig + 4]);
            }

            if (kq == 2) {
                // Issue stage t+2 mid-iteration (empty group in the tail
                // keeps the wait_group accounting uniform).
                if (t + 2 < T) {
                    int s2 = s + 2; if (s2 >= 3) s2 -= 3;
                    const int k0 = (t + 2) * 32;
                    ISSUE_STAGE(s2, k0);
                }
                asm volatile("cp.async.commit_group;");
            }

#pragma unroll
            for (int mi = 0; mi < 4; mi++)
#pragma unroll
                for (int ni = 0; ni < 8; ni++) {
                    asm volatile(
                        "mma.sync.aligned.m16n8k8.row.col.f32.tf32.tf32.f32 "
                        "{%0,%1,%2,%3}, {%4,%5,%6,%7}, {%8,%9}, {%0,%1,%2,%3};\n"
                        : "+f"(acc[mi][ni][0]), "+f"(acc[mi][ni][1]),
                          "+f"(acc[mi][ni][2]), "+f"(acc[mi][ni][3])
                        : "r"(af[mi][0]), "r"(af[mi][1]),
                          "r"(af[mi][2]), "r"(af[mi][3]),
                          "r"(bf[ni][0]), "r"(bf[ni][1]));
                }
        }

        asm volatile("cp.async.wait_group 1;");
        __syncthreads();
        if (++s == 3) s = 0;
    }
#undef ISSUE_STAGE

    // Epilogue
#pragma unroll
    for (int mi = 0; mi < 4; mi++) {
        int r = bm + warp_m * 64 + mi * 16 + gID;
#pragma unroll
        for (int ni = 0; ni < 8; ni++) {
            int c = bn + warp_n * 64 + ni * 8 + tig * 2;
            float2 lo, hi;
            lo.x = acc[mi][ni][0]; lo.y = acc[mi][ni][1];
            hi.x = acc[mi][ni][2]; hi.y = acc[mi][ni][3];
            if (HAS_SCALE) {
                lo.x *= alpha; lo.y *= alpha; hi.x *= alpha; hi.y *= alpha;
            }
            if (HAS_BIAS) {
                float b0 = bias[c], b1 = bias[c + 1];
                lo.x += b0; lo.y += b1; hi.x += b0; hi.y += b1;
            }
            if (CVT_OUT) {
                lo.x = to_tf32(lo.x); lo.y = to_tf32(lo.y);
                hi.x = to_tf32(hi.x); hi.y = to_tf32(hi.y);
            }
            *(float2*)&C[(long long)r * ldc + c]       = lo;
            *(float2*)&C[(long long)(r + 8) * ldc + c] = hi;
        }
    }
}

// ---------------------------------------------------------------------------
// Convert-copy: out[i] = tf32(in[i])
// ---------------------------------------------------------------------------
__global__ __launch_bounds__(256)
void cvt_copy(const float* __restrict__ in, float* __restrict__ out, int n4)
{
    int i = blockIdx.x * blockDim.x + threadIdx.x;
    if (i < n4) {
        float4 v = ((const float4*)in)[i];
        v.x = to_tf32(v.x); v.y = to_tf32(v.y);
        v.z = to_tf32(v.z); v.w = to_tf32(v.w);
        ((float4*)out)[i] = v;
    }
}

__global__ void pack_bias(const float* __restrict__ b0,
                          const float* __restrict__ b1,
                          const float* __restrict__ b2,
                          float* __restrict__ out)
{
    int i = threadIdx.x + blockIdx.x * blockDim.x;
    if (i < DIM) {
        out[i]           = b0[i];
        out[i + DIM]     = b1[i];
        out[i + 2 * DIM] = b2[i];
    }
}

// ---------------------------------------------------------------------------
// Tiled transpose with tf32 rounding: out[c][r] = tf32(in[r][c])
// ---------------------------------------------------------------------------
__global__ __launch_bounds__(256)
void transpose_cvt(const float* __restrict__ in, float* __restrict__ out,
                   int rows, int cols)
{
    __shared__ float tile[32][33];
    const long long zoff = (long long)blockIdx.z * rows * cols;
    int c = blockIdx.x * 32 + threadIdx.x;
    int r = blockIdx.y * 32 + threadIdx.y;
#pragma unroll
    for (int j = 0; j < 32; j += 8)
        tile[threadIdx.y + j][threadIdx.x] = in[zoff + (long long)(r + j) * cols + c];
    __syncthreads();
    int c2 = blockIdx.y * 32 + threadIdx.x;
    int r2 = blockIdx.x * 32 + threadIdx.y;
#pragma unroll
    for (int j = 0; j < 32; j += 8)
        out[zoff + (long long)(r2 + j) * rows + c2] =
            to_tf32(tile[threadIdx.x][threadIdx.y + j]);
}

// ---------------------------------------------------------------------------
// Row softmax; output rounded to tf32 (feeds PV GEMM as A operand)
// ---------------------------------------------------------------------------
__global__ __launch_bounds__(256)
void softmax_rows(float* __restrict__ Sbuf)
{
    float* p = Sbuf + (size_t)blockIdx.x * SEQ;
    const int tid = threadIdx.x;

    float v[8];
    *(float4*)&v[0] = *(const float4*)&p[tid * 8 + 0];
    *(float4*)&v[4] = *(const float4*)&p[tid * 8 + 4];

    float mx = -1e30f;
#pragma unroll
    for (int i = 0; i < 8; i++) mx = fmaxf(mx, v[i]);

    __shared__ float red[8];
    __shared__ float bcast;
#pragma unroll
    for (int o = 16; o > 0; o >>= 1)
        mx = fmaxf(mx, __shfl_xor_sync(0xffffffffu, mx, o));
    if ((tid & 31) == 0) red[tid >> 5] = mx;
    __syncthreads();
    if (tid < 32) {
        float m = (tid < 8) ? red[tid] : -1e30f;
#pragma unroll
        for (int o = 4; o > 0; o >>= 1)
            m = fmaxf(m, __shfl_xor_sync(0xffffffffu, m, o));
        if (tid == 0) bcast = m;
    }
    __syncthreads();
    mx = bcast;
    __syncthreads();

    float sum = 0.f;
#pragma unroll
    for (int i = 0; i < 8; i++) { v[i] = expf(v[i] - mx); sum += v[i]; }

#pragma unroll
    for (int o = 16; o > 0; o >>= 1)
        sum += __shfl_xor_sync(0xffffffffu, sum, o);
    if ((tid & 31) == 0) red[tid >> 5] = sum;
    __syncthreads();
    if (tid < 32) {
        float s = (tid < 8) ? red[tid] : 0.f;
#pragma unroll
        for (int o = 4; o > 0; o >>= 1)
            s += __shfl_xor_sync(0xffffffffu, s, o);
        if (tid == 0) bcast = s;
    }
    __syncthreads();
    float inv = 1.0f / bcast;

#pragma unroll
    for (int i = 0; i < 8; i++) v[i] = to_tf32(v[i] * inv);
    *(float4*)&p[tid * 8 + 0] = *(const float4*)&v[0];
    *(float4*)&p[tid * 8 + 4] = *(const float4*)&v[4];
}

// ---------------------------------------------------------------------------
extern "C" void kernel_launch(void* const* d_in, const int* in_sizes, int n_in,
                              void* d_out, int out_size)
{
    const float* X  = (const float*)d_in[0];
    const float* Wq = (const float*)d_in[1];
    const float* bq = (const float*)d_in[2];
    const float* Wk = (const float*)d_in[3];
    const float* bk = (const float*)d_in[4];
    const float* Wv = (const float*)d_in[5];
    const float* bv = (const float*)d_in[6];
    float* out = (float*)d_out;

    float *Xc, *QKV, *Vt, *Wt, *b3, *Sc;
    cudaGetSymbolAddress((void**)&Xc,  g_Xc);
    cudaGetSymbolAddress((void**)&QKV, g_QKV);
    cudaGetSymbolAddress((void**)&Vt,  g_Vt);
    cudaGetSymbolAddress((void**)&Wt,  g_Wt);
    cudaGetSymbolAddress((void**)&b3,  g_b3);
    cudaGetSymbolAddress((void**)&Sc,  g_S);

    const float scale = 1.0f / sqrtf((float)DIM);
    const long long QKVs = (long long)BATCH * SEQ * DIM;
    const int SMEM = 3 * ST_F * 4;   // 165888 B

    static bool attr_set = false;
    if (!attr_set) {
        cudaFuncSetAttribute(tf32gemm_big<true, false, true>,
                             cudaFuncAttributeMaxDynamicSharedMemorySize, SMEM);
        cudaFuncSetAttribute(tf32gemm_big<false, true, false>,
                             cudaFuncAttributeMaxDynamicSharedMemorySize, SMEM);
        cudaFuncSetAttribute(tf32gemm_big<false, false, false>,
                             cudaFuncAttributeMaxDynamicSharedMemorySize, SMEM);
        attr_set = true;
    }

    // 0) Pre-round X; transpose+round weights; pack biases
    {
        int n4 = BATCH * SEQ * DIM / 4;
        cvt_copy<<<(n4 + 255) / 256, 256>>>(X, Xc, n4);

        dim3 tgrid(DIM / 32, DIM / 32, 1);
        dim3 tblk(32, 8, 1);
        transpose_cvt<<<tgrid, tblk>>>(Wq, Wt,                 DIM, DIM);
        transpose_cvt<<<tgrid, tblk>>>(Wk, Wt + DIM * DIM,     DIM, DIM);
        transpose_cvt<<<tgrid, tblk>>>(Wv, Wt + 2 * DIM * DIM, DIM, DIM);
        pack_bias<<<2, 256>>>(bq, bk, bv, b3);
    }

    // 1) Fused QKV projections: z in {0,1,2}
    {
        dim3 grid(DIM / 256, (BATCH * SEQ) / 128, 3);
        tf32gemm_big<true, false, true><<<grid, 256, SMEM>>>(
            BATCH * SEQ, DIM, DIM,
            Xc, DIM, 0,
            Wt, DIM, (long long)DIM * DIM,
            QKV, DIM, QKVs,
            1.0f, b3, DIM);
    }

    // 2) V transpose per batch: V[b][t][d] -> Vt[b][d][t] (re-round)
    {
        dim3 tgrid(DIM / 32, SEQ / 32, BATCH);
        dim3 tblk(32, 8, 1);
        transpose_cvt<<<tgrid, tblk>>>(QKV + 2 * QKVs, Vt, SEQ, DIM);
    }

    // 3) scores = Q @ K^T * 1/sqrt(d)
    {
        dim3 grid(SEQ / 256, SEQ / 128, BATCH);
        tf32gemm_big<false, true, false><<<grid, 256, SMEM>>>(
            SEQ, SEQ, DIM,
            QKV, DIM, (long long)SEQ * DIM,
            QKV + QKVs, DIM, (long long)SEQ * DIM,
            Sc, SEQ, (long long)SEQ * SEQ,
            scale, nullptr, 0);
    }

    // 4) row softmax (writes tf32-rounded P)
    softmax_rows<<<BATCH * SEQ, 256>>>(Sc);

    // 5) out = P @ V  (B = Vt[b][d][t] = [N][K])
    {
        dim3 grid(DIM / 256, SEQ / 128, BATCH);
        tf32gemm_big<false, false, false><<<grid, 256, SMEM>>>(
            SEQ, DIM, SEQ,
            Sc, SEQ, (long long)SEQ * SEQ,
            Vt, SEQ, (long long)SEQ * DIM,
            out, DIM, (long long)SEQ * DIM,
            1.0f, nullptr, 0);
    }
}

// round 6
// speedup vs baseline: 1.6894x; 1.6894x over previous
#include <cuda_runtime.h>
#include <cuda_fp16.h>
#include <math.h>
#include <stdint.h>

#define BATCH 4
#define SEQ   2048
#define DIM   512

// Scratch (__device__ globals — allocation-free per harness rules)
__device__ __half g_Xh [BATCH * SEQ * DIM];            // 8 MB   X in half
__device__ __half g_QKV[3 * BATCH * SEQ * DIM];        // 24 MB  Q,K,V half
__device__ __half g_Vt [BATCH * SEQ * DIM];            // 8 MB   V^T half [b][d][t]
__device__ __half g_Wt [3 * DIM * DIM];                // 1.5 MB W^T half packed
__device__ float  g_b3 [3 * DIM];                      // biases packed fp32
__device__ float  g_S  [(size_t)BATCH * SEQ * SEQ];    // 64 MB  scores fp32
__device__ __half g_P  [(size_t)BATCH * SEQ * SEQ];    // 32 MB  probs half

// ---------------------------------------------------------------------------
__device__ __forceinline__ void cpa16(__half* dst, const __half* src)
{
    uint32_t d = (uint32_t)__cvta_generic_to_shared(dst);
    asm volatile("cp.async.cg.shared.global [%0], [%1], 16;" :: "r"(d), "l"(src));
}

// ---------------------------------------------------------------------------
// 3-stage pipelined FP16 mma.sync GEMM: C = alpha * A[MxK] @ B[NxK]^T (+bias)
// A,B half row-major. Block tile 128x256, k-tile 64 halves (128 B rows).
// 8 warps (2 M x 4 N), warp tile 64x64, mma m16n8k16 (fp32 accum).
// smem: 3 stages x (128+256) rows x 72 halves = 165888 B. 1 CTA/SM.
// ---------------------------------------------------------------------------
#define PW   36      // row pitch in 32-bit words (72 halves)
#define AH   9216    // halves in A part of a stage (128*72)
#define ST_H 27648   // halves per stage ((128+256)*72)

template <bool HAS_BIAS, bool HAS_SCALE, bool OUT_HALF>
__global__ __launch_bounds__(256, 1)
void h16gemm(int M, int N, int K,
             const __half* __restrict__ A, int lda, long long sA,
             const __half* __restrict__ B, int ldb, long long sB,
             void* __restrict__ Cv, int ldc, long long sC,
             float alpha, const float* __restrict__ bias, long long sBias)
{
    extern __shared__ __half smh[];

    A += (long long)blockIdx.z * sA;
    B += (long long)blockIdx.z * sB;
    if (HAS_BIAS) bias += (long long)blockIdx.z * sBias;

    const int tid    = threadIdx.x;
    const int wid    = tid >> 5;
    const int lane   = tid & 31;
    const int gID    = lane >> 2;   // 0..7
    const int tig    = lane & 3;    // 0..3
    const int warp_m = wid & 1;     // 2 warps along M
    const int warp_n = wid >> 1;    // 4 warps along N

    const int bm = blockIdx.y * 128;
    const int bn = blockIdx.x * 256;

    // cp.async mapping: 16B chunks (8 halves). A: 128 rows x 8 = 1024 chunks
    // -> 4/thread; B: 256 rows x 8 = 2048 -> 8/thread.
    const int lrow = tid >> 3;        // 0..31 (+32*i)
    const int lc8  = (tid & 7) * 8;   // half offset within 64-half k-row

    const __half* Ap = A + (long long)(bm + lrow) * lda + lc8;
    const __half* Bp = B + (long long)(bn + lrow) * ldb + lc8;
    const int soff = lrow * 72 + lc8;   // + i*2304 (=32*72)

    const int T = K >> 6;   // 64 halves per k-tile

#define ISSUE_STAGE(s, k0)                                                  \
    do {                                                                    \
        __half* sa_ = smh + (s) * ST_H;                                     \
        __half* sb_ = sa_ + AH;                                             \
        _Pragma("unroll")                                                   \
        for (int i_ = 0; i_ < 4; i_++)                                      \
            cpa16(sa_ + soff + i_ * 2304,                                   \
                  Ap + (k0) + (long long)i_ * 32 * lda);                    \
        _Pragma("unroll")                                                   \
        for (int i_ = 0; i_ < 8; i_++)                                      \
            cpa16(sb_ + soff + i_ * 2304,                                   \
                  Bp + (k0) + (long long)i_ * 32 * ldb);                    \
    } while (0)

    // Prologue: stages 0 and 1
    ISSUE_STAGE(0, 0);
    asm volatile("cp.async.commit_group;");
    if (T > 1) ISSUE_STAGE(1, 64);
    asm volatile("cp.async.commit_group;");

    float acc[4][8][4];
#pragma unroll
    for (int mi = 0; mi < 4; mi++)
#pragma unroll
        for (int ni = 0; ni < 8; ni++)
#pragma unroll
            for (int t = 0; t < 4; t++) acc[mi][ni][t] = 0.f;

    asm volatile("cp.async.wait_group 1;");
    __syncthreads();

    int s = 0;
    for (int t = 0; t < T; t++) {
        const uint32_t* Aw = (const uint32_t*)(smh + s * ST_H);
        const uint32_t* Bw = (const uint32_t*)(smh + s * ST_H + AH);

#pragma unroll
        for (int kq = 0; kq < 4; kq++) {        // 4 k16-steps per 64-half tile
            const int kw = kq * 8;              // word offset
            uint32_t af[4][4], bf[8][2];
#pragma unroll
            for (int mi = 0; mi < 4; mi++) {
                int m = warp_m * 64 + mi * 16 + gID;
                af[mi][0] = Aw[m * PW + kw + tig];
                af[mi][1] = Aw[(m + 8) * PW + kw + tig];
                af[mi][2] = Aw[m * PW + kw + tig + 4];
                af[mi][3] = Aw[(m + 8) * PW + kw + tig + 4];
            }
#pragma unroll
            for (int ni = 0; ni < 8; ni++) {
                int n = warp_n * 64 + ni * 8 + gID;
                bf[ni][0] = Bw[n * PW + kw + tig];
                bf[ni][1] = Bw[n * PW + kw + tig + 4];
            }

            if (kq == 2) {
                if (t + 2 < T) {
                    int s2 = s + 2; if (s2 >= 3) s2 -= 3;
                    ISSUE_STAGE(s2, (t + 2) * 64);
                }
                asm volatile("cp.async.commit_group;");
            }

#pragma unroll
            for (int mi = 0; mi < 4; mi++)
#pragma unroll
                for (int ni = 0; ni < 8; ni++) {
                    asm volatile(
                        "mma.sync.aligned.m16n8k16.row.col.f32.f16.f16.f32 "
                        "{%0,%1,%2,%3}, {%4,%5,%6,%7}, {%8,%9}, {%0,%1,%2,%3};\n"
                        : "+f"(acc[mi][ni][0]), "+f"(acc[mi][ni][1]),
                          "+f"(acc[mi][ni][2]), "+f"(acc[mi][ni][3])
                        : "r"(af[mi][0]), "r"(af[mi][1]),
                          "r"(af[mi][2]), "r"(af[mi][3]),
                          "r"(bf[ni][0]), "r"(bf[ni][1]));
                }
        }

        asm volatile("cp.async.wait_group 1;");
        __syncthreads();
        if (++s == 3) s = 0;
    }
#undef ISSUE_STAGE

    // Epilogue
    __half* Ch = (__half*)Cv + (OUT_HALF ? (long long)blockIdx.z * sC : 0);
    float*  Cf = (float*)Cv  + (OUT_HALF ? 0 : (long long)blockIdx.z * sC);

#pragma unroll
    for (int mi = 0; mi < 4; mi++) {
        int r = bm + warp_m * 64 + mi * 16 + gID;
#pragma unroll
        for (int ni = 0; ni < 8; ni++) {
            int c = bn + warp_n * 64 + ni * 8 + tig * 2;
            float v0 = acc[mi][ni][0], v1 = acc[mi][ni][1];
            float v2 = acc[mi][ni][2], v3 = acc[mi][ni][3];
            if (HAS_SCALE) { v0 *= alpha; v1 *= alpha; v2 *= alpha; v3 *= alpha; }
            if (HAS_BIAS) {
                float b0 = bias[c], b1 = bias[c + 1];
                v0 += b0; v1 += b1; v2 += b0; v3 += b1;
            }
            if (OUT_HALF) {
                *(__half2*)&Ch[(long long)r * ldc + c] =
                    __floats2half2_rn(v0, v1);
                *(__half2*)&Ch[(long long)(r + 8) * ldc + c] =
                    __floats2half2_rn(v2, v3);
            } else {
                float2 lo; lo.x = v0; lo.y = v1;
                float2 hi; hi.x = v2; hi.y = v3;
                *(float2*)&Cf[(long long)r * ldc + c]       = lo;
                *(float2*)&Cf[(long long)(r + 8) * ldc + c] = hi;
            }
        }
    }
}

// ---------------------------------------------------------------------------
// fp32 -> half convert-copy
// ---------------------------------------------------------------------------
__global__ __launch_bounds__(256)
void cvt_f2h(const float* __restrict__ in, __half* __restrict__ out, int n4)
{
    int i = blockIdx.x * blockDim.x + threadIdx.x;
    if (i < n4) {
        float4 v = ((const float4*)in)[i];
        __half2 a = __floats2half2_rn(v.x, v.y);
        __half2 b = __floats2half2_rn(v.z, v.w);
        *(__half2*)&out[i * 4]     = a;
        *(__half2*)&out[i * 4 + 2] = b;
    }
}

__global__ void pack_bias(const float* __restrict__ b0,
                          const float* __restrict__ b1,
                          const float* __restrict__ b2,
                          float* __restrict__ out)
{
    int i = threadIdx.x + blockIdx.x * blockDim.x;
    if (i < DIM) {
        out[i]           = b0[i];
        out[i + DIM]     = b1[i];
        out[i + 2 * DIM] = b2[i];
    }
}

// ---------------------------------------------------------------------------
// Transpose fp32 -> half: out[c][r] = half(in[r][c])
// ---------------------------------------------------------------------------
__global__ __launch_bounds__(256)
void transpose_f2h(const float* __restrict__ in, __half* __restrict__ out,
                   int rows, int cols)
{
    __shared__ float tile[32][33];
    const long long zoff = (long long)blockIdx.z * rows * cols;
    int c = blockIdx.x * 32 + threadIdx.x;
    int r = blockIdx.y * 32 + threadIdx.y;
#pragma unroll
    for (int j = 0; j < 32; j += 8)
        tile[threadIdx.y + j][threadIdx.x] = in[zoff + (long long)(r + j) * cols + c];
    __syncthreads();
    int c2 = blockIdx.y * 32 + threadIdx.x;
    int r2 = blockIdx.x * 32 + threadIdx.y;
#pragma unroll
    for (int j = 0; j < 32; j += 8)
        out[zoff + (long long)(r2 + j) * rows + c2] =
            __float2half_rn(tile[threadIdx.x][threadIdx.y + j]);
}

// ---------------------------------------------------------------------------
// Transpose half -> half: out[c][r] = in[r][c]
// ---------------------------------------------------------------------------
__global__ __launch_bounds__(256)
void transpose_h2h(const __half* __restrict__ in, __half* __restrict__ out,
                   int rows, int cols)
{
    __shared__ __half tile[32][34];
    const long long zoff = (long long)blockIdx.z * rows * cols;
    int c = blockIdx.x * 32 + threadIdx.x;
    int r = blockIdx.y * 32 + threadIdx.y;
#pragma unroll
    for (int j = 0; j < 32; j += 8)
        tile[threadIdx.y + j][threadIdx.x] = in[zoff + (long long)(r + j) * cols + c];
    __syncthreads();
    int c2 = blockIdx.y * 32 + threadIdx.x;
    int r2 = blockIdx.x * 32 + threadIdx.y;
#pragma unroll
    for (int j = 0; j < 32; j += 8)
        out[zoff + (long long)(r2 + j) * rows + c2] = tile[threadIdx.x][threadIdx.y + j];
}

// ---------------------------------------------------------------------------
// Row softmax: fp32 scores in, half probs out
// ---------------------------------------------------------------------------
__global__ __launch_bounds__(256)
void softmax_rows(const float* __restrict__ Sbuf, __half* __restrict__ Pbuf)
{
    const float* p = Sbuf + (size_t)blockIdx.x * SEQ;
    __half* q = Pbuf + (size_t)blockIdx.x * SEQ;
    const int tid = threadIdx.x;

    float v[8];
    *(float4*)&v[0] = *(const float4*)&p[tid * 8 + 0];
    *(float4*)&v[4] = *(const float4*)&p[tid * 8 + 4];

    float mx = -1e30f;
#pragma unroll
    for (int i = 0; i < 8; i++) mx = fmaxf(mx, v[i]);

    __shared__ float red[8];
    __shared__ float bcast;
#pragma unroll
    for (int o = 16; o > 0; o >>= 1)
        mx = fmaxf(mx, __shfl_xor_sync(0xffffffffu, mx, o));
    if ((tid & 31) == 0) red[tid >> 5] = mx;
    __syncthreads();
    if (tid < 32) {
        float m = (tid < 8) ? red[tid] : -1e30f;
#pragma unroll
        for (int o = 4; o > 0; o >>= 1)
            m = fmaxf(m, __shfl_xor_sync(0xffffffffu, m, o));
        if (tid == 0) bcast = m;
    }
    __syncthreads();
    mx = bcast;
    __syncthreads();

    float sum = 0.f;
#pragma unroll
    for (int i = 0; i < 8; i++) { v[i] = expf(v[i] - mx); sum += v[i]; }

#pragma unroll
    for (int o = 16; o > 0; o >>= 1)
        sum += __shfl_xor_sync(0xffffffffu, sum, o);
    if ((tid & 31) == 0) red[tid >> 5] = sum;
    __syncthreads();
    if (tid < 32) {
        float s = (tid < 8) ? red[tid] : 0.f;
#pragma unroll
        for (int o = 4; o > 0; o >>= 1)
            s += __shfl_xor_sync(0xffffffffu, s, o);
        if (tid == 0) bcast = s;
    }
    __syncthreads();
    float inv = 1.0f / bcast;

#pragma unroll
    for (int i = 0; i < 4; i++) {
        __half2 h = __floats2half2_rn(v[2 * i] * inv, v[2 * i + 1] * inv);
        *(__half2*)&q[tid * 8 + 2 * i] = h;
    }
}

// ---------------------------------------------------------------------------
extern "C" void kernel_launch(void* const* d_in, const int* in_sizes, int n_in,
                              void* d_out, int out_size)
{
    const float* X  = (const float*)d_in[0];
    const float* Wq = (const float*)d_in[1];
    const float* bq = (const float*)d_in[2];
    const float* Wk = (const float*)d_in[3];
    const float* bk = (const float*)d_in[4];
    const float* Wv = (const float*)d_in[5];
    const float* bv = (const float*)d_in[6];
    float* out = (float*)d_out;

    __half *Xh, *QKV, *Vt, *Wt, *P;
    float  *b3, *Sc;
    cudaGetSymbolAddress((void**)&Xh,  g_Xh);
    cudaGetSymbolAddress((void**)&QKV, g_QKV);
    cudaGetSymbolAddress((void**)&Vt,  g_Vt);
    cudaGetSymbolAddress((void**)&Wt,  g_Wt);
    cudaGetSymbolAddress((void**)&b3,  g_b3);
    cudaGetSymbolAddress((void**)&Sc,  g_S);
    cudaGetSymbolAddress((void**)&P,   g_P);

    const float scale = 1.0f / sqrtf((float)DIM);
    const long long QKVs = (long long)BATCH * SEQ * DIM;
    const int SMEM = 3 * ST_H * 2;   // 165888 B

    static bool attr_set = false;
    if (!attr_set) {
        cudaFuncSetAttribute(h16gemm<true, false, true>,
                             cudaFuncAttributeMaxDynamicSharedMemorySize, SMEM);
        cudaFuncSetAttribute(h16gemm<false, true, false>,
                             cudaFuncAttributeMaxDynamicSharedMemorySize, SMEM);
        cudaFuncSetAttribute(h16gemm<false, false, false>,
                             cudaFuncAttributeMaxDynamicSharedMemorySize, SMEM);
        attr_set = true;
    }

    // 0) X -> half; W transpose+convert; pack biases
    {
        int n4 = BATCH * SEQ * DIM / 4;
        cvt_f2h<<<(n4 + 255) / 256, 256>>>(X, Xh, n4);

        dim3 tgrid(DIM / 32, DIM / 32, 1);
        dim3 tblk(32, 8, 1);
        transpose_f2h<<<tgrid, tblk>>>(Wq, Wt,                 DIM, DIM);
        transpose_f2h<<<tgrid, tblk>>>(Wk, Wt + DIM * DIM,     DIM, DIM);
        transpose_f2h<<<tgrid, tblk>>>(Wv, Wt + 2 * DIM * DIM, DIM, DIM);
        pack_bias<<<2, 256>>>(bq, bk, bv, b3);
    }

    // 1) Fused QKV projections (half out): z in {0,1,2}
    {
        dim3 grid(DIM / 256, (BATCH * SEQ) / 128, 3);
        h16gemm<true, false, true><<<grid, 256, SMEM>>>(
            BATCH * SEQ, DIM, DIM,
            Xh, DIM, 0,
            Wt, DIM, (long long)DIM * DIM,
            QKV, DIM, QKVs,
            1.0f, b3, DIM);
    }

    // 2) V transpose per batch: V[b][t][d] -> Vt[b][d][t]
    {
        dim3 tgrid(DIM / 32, SEQ / 32, BATCH);
        dim3 tblk(32, 8, 1);
        transpose_h2h<<<tgrid, tblk>>>(QKV + 2 * QKVs, Vt, SEQ, DIM);
    }

    // 3) scores = Q @ K^T * 1/sqrt(d)  (fp32 out)
    {
        dim3 grid(SEQ / 256, SEQ / 128, BATCH);
        h16gemm<false, true, false><<<grid, 256, SMEM>>>(
            SEQ, SEQ, DIM,
            QKV, DIM, (long long)SEQ * DIM,
            QKV + QKVs, DIM, (long long)SEQ * DIM,
            Sc, SEQ, (long long)SEQ * SEQ,
            scale, nullptr, 0);
    }

    // 4) row softmax: fp32 scores -> half probs
    softmax_rows<<<BATCH * SEQ, 256>>>(Sc, P);

    // 5) out = P @ V  (B = Vt[b][d][t] = [N][K]; fp32 out)
    {
        dim3 grid(DIM / 256, SEQ / 128, BATCH);
        h16gemm<false, false, false><<<grid, 256, SMEM>>>(
            SEQ, DIM, SEQ,
            P, SEQ, (long long)SEQ * SEQ,
            Vt, SEQ, (long long)SEQ * DIM,
            out, DIM, (long long)SEQ * DIM,
            1.0f, nullptr, 0);
    }
}

// round 7
// speedup vs baseline: 1.9096x; 1.1303x over previous
#include <cuda_runtime.h>
#include <cuda_fp16.h>
#include <math.h>
#include <stdint.h>

#define BATCH 4
#define SEQ   2048
#define DIM   512

// Scratch (__device__ globals — allocation-free per harness rules)
__device__ __half g_Xh [BATCH * SEQ * DIM];            // 8 MB   X in half
__device__ __half g_QKV[3 * BATCH * SEQ * DIM];        // 24 MB  Q,K,V half
__device__ __half g_Vt [BATCH * SEQ * DIM];            // 8 MB   V^T half [b][d][t]
__device__ __half g_Wt [3 * DIM * DIM];                // 1.5 MB W^T half packed
__device__ float  g_b3 [3 * DIM];                      // biases packed fp32
__device__ float  g_S  [(size_t)BATCH * SEQ * SEQ];    // 64 MB  scores fp32
__device__ __half g_P  [(size_t)BATCH * SEQ * SEQ];    // 32 MB  probs half

// ---------------------------------------------------------------------------
__device__ __forceinline__ void cpa16(__half* dst, const __half* src)
{
    uint32_t d = (uint32_t)__cvta_generic_to_shared(dst);
    asm volatile("cp.async.cg.shared.global [%0], [%1], 16;" :: "r"(d), "l"(src));
}

__device__ __forceinline__ void ldm_x4(uint32_t& r0, uint32_t& r1,
                                       uint32_t& r2, uint32_t& r3, uint32_t a)
{
    asm volatile("ldmatrix.sync.aligned.m8n8.x4.shared.b16 {%0,%1,%2,%3}, [%4];"
                 : "=r"(r0), "=r"(r1), "=r"(r2), "=r"(r3) : "r"(a));
}

// ---------------------------------------------------------------------------
// 3-stage pipelined FP16 mma.sync GEMM with ldmatrix fragment loads.
// C = alpha * A[MxK] @ B[NxK]^T (+bias). A,B half row-major.
// Block tile 128x256, k-tile 64 halves (128 B rows, pitch 72 halves).
// 8 warps (2 M x 4 N), warp tile 64x64, mma m16n8k16 (fp32 accum).
// smem: 3 stages x (128+256) x 72 halves = 165888 B. 1 CTA/SM.
// ---------------------------------------------------------------------------
#define PW    36       // row pitch in 32-bit words (72 halves)
#define AH    9216     // halves in A part of a stage (128*72)
#define ST_H  27648    // halves per stage ((128+256)*72)
#define ST_B  55296    // bytes per stage

template <bool HAS_BIAS, bool HAS_SCALE, bool OUT_HALF>
__global__ __launch_bounds__(256, 1)
void h16gemm(int M, int N, int K,
             const __half* __restrict__ A, int lda, long long sA,
             const __half* __restrict__ B, int ldb, long long sB,
             void* __restrict__ Cv, int ldc, long long sC,
             float alpha, const float* __restrict__ bias, long long sBias)
{
    extern __shared__ __half smh[];

    A += (long long)blockIdx.z * sA;
    B += (long long)blockIdx.z * sB;
    if (HAS_BIAS) bias += (long long)blockIdx.z * sBias;

    const int tid    = threadIdx.x;
    const int wid    = tid >> 5;
    const int lane   = tid & 31;
    const int gID    = lane >> 2;   // 0..7
    const int tig    = lane & 3;    // 0..3
    const int warp_m = wid & 1;     // 2 warps along M
    const int warp_n = wid >> 1;    // 4 warps along N

    const int bm = blockIdx.y * 128;
    const int bn = blockIdx.x * 256;

    // cp.async mapping: 16B chunks (8 halves). A: 1024 chunks -> 4/thread;
    // B: 2048 -> 8/thread.
    const int lrow = tid >> 3;        // 0..31 (+32*i)
    const int lc8  = (tid & 7) * 8;   // half offset within 64-half k-row

    const __half* Ap = A + (long long)(bm + lrow) * lda + lc8;
    const __half* Bp = B + (long long)(bn + lrow) * ldb + lc8;
    const int soff = lrow * 72 + lc8;   // + i*2304 (=32*72)

    // ldmatrix per-lane base addresses (bytes, shared space)
    const uint32_t sb0 = (uint32_t)__cvta_generic_to_shared(smh);
    const int l7  = lane & 7;
    const int l8  = (lane >> 3) & 1;
    const int l16 = (lane >> 4) & 1;
    // A fragments: matrices (row lo,k lo)(row hi,k lo)(row lo,k hi)(row hi,k hi)
    const uint32_t aAddr = sb0 +
        (uint32_t)(((warp_m * 64 + l7 + l8 * 8) * 72) + l16 * 8) * 2;
    // B fragments: matrices (n lo,k lo)(n lo,k hi)(n hi,k lo)(n hi,k hi)
    const uint32_t bAddr = sb0 + AH * 2 +
        (uint32_t)(((warp_n * 64 + l7 + l16 * 8) * 72) + l8 * 8) * 2;

    const int T = K >> 6;   // 64 halves per k-tile

#define ISSUE_STAGE(s, k0)                                                  \
    do {                                                                    \
        __half* sa_ = smh + (s) * ST_H;                                     \
        __half* sb_ = sa_ + AH;                                             \
        _Pragma("unroll")                                                   \
        for (int i_ = 0; i_ < 4; i_++)                                      \
            cpa16(sa_ + soff + i_ * 2304,                                   \
                  Ap + (k0) + (long long)i_ * 32 * lda);                    \
        _Pragma("unroll")                                                   \
        for (int i_ = 0; i_ < 8; i_++)                                      \
            cpa16(sb_ + soff + i_ * 2304,                                   \
                  Bp + (k0) + (long long)i_ * 32 * ldb);                    \
    } while (0)

    ISSUE_STAGE(0, 0);
    asm volatile("cp.async.commit_group;");
    if (T > 1) ISSUE_STAGE(1, 64);
    asm volatile("cp.async.commit_group;");

    float acc[4][8][4];
#pragma unroll
    for (int mi = 0; mi < 4; mi++)
#pragma unroll
        for (int ni = 0; ni < 8; ni++)
#pragma unroll
            for (int t = 0; t < 4; t++) acc[mi][ni][t] = 0.f;

    asm volatile("cp.async.wait_group 1;");
    __syncthreads();

    int s = 0;
    for (int t = 0; t < T; t++) {
        const uint32_t aS = aAddr + s * ST_B;
        const uint32_t bS = bAddr + s * ST_B;

#pragma unroll
        for (int kq = 0; kq < 4; kq++) {      // 4 k16-steps per 64-half tile
            const uint32_t ko = kq * 32;      // bytes (16 halves)
            uint32_t af[4][4], bf[8][2];
#pragma unroll
            for (int mi = 0; mi < 4; mi++)
                ldm_x4(af[mi][0], af[mi][1], af[mi][2], af[mi][3],
                       aS + mi * 2304 + ko);
#pragma unroll
            for (int np = 0; np < 4; np++)
                ldm_x4(bf[2 * np][0], bf[2 * np][1],
                       bf[2 * np + 1][0], bf[2 * np + 1][1],
                       bS + np * 2304 + ko);

            if (kq == 2) {
                if (t + 2 < T) {
                    int s2 = s + 2; if (s2 >= 3) s2 -= 3;
                    ISSUE_STAGE(s2, (t + 2) * 64);
                }
                asm volatile("cp.async.commit_group;");
            }

#pragma unroll
            for (int mi = 0; mi < 4; mi++)
#pragma unroll
                for (int ni = 0; ni < 8; ni++) {
                    asm volatile(
                        "mma.sync.aligned.m16n8k16.row.col.f32.f16.f16.f32 "
                        "{%0,%1,%2,%3}, {%4,%5,%6,%7}, {%8,%9}, {%0,%1,%2,%3};\n"
                        : "+f"(acc[mi][ni][0]), "+f"(acc[mi][ni][1]),
                          "+f"(acc[mi][ni][2]), "+f"(acc[mi][ni][3])
                        : "r"(af[mi][0]), "r"(af[mi][1]),
                          "r"(af[mi][2]), "r"(af[mi][3]),
                          "r"(bf[ni][0]), "r"(bf[ni][1]));
                }
        }

        asm volatile("cp.async.wait_group 1;");
        __syncthreads();
        if (++s == 3) s = 0;
    }
#undef ISSUE_STAGE

    // Epilogue
    __half* Ch = (__half*)Cv + (OUT_HALF ? (long long)blockIdx.z * sC : 0);
    float*  Cf = (float*)Cv  + (OUT_HALF ? 0 : (long long)blockIdx.z * sC);

#pragma unroll
    for (int mi = 0; mi < 4; mi++) {
        int r = bm + warp_m * 64 + mi * 16 + gID;
#pragma unroll
        for (int ni = 0; ni < 8; ni++) {
            int c = bn + warp_n * 64 + ni * 8 + tig * 2;
            float v0 = acc[mi][ni][0], v1 = acc[mi][ni][1];
            float v2 = acc[mi][ni][2], v3 = acc[mi][ni][3];
            if (HAS_SCALE) { v0 *= alpha; v1 *= alpha; v2 *= alpha; v3 *= alpha; }
            if (HAS_BIAS) {
                float b0 = bias[c], b1 = bias[c + 1];
                v0 += b0; v1 += b1; v2 += b0; v3 += b1;
            }
            if (OUT_HALF) {
                *(__half2*)&Ch[(long long)r * ldc + c] =
                    __floats2half2_rn(v0, v1);
                *(__half2*)&Ch[(long long)(r + 8) * ldc + c] =
                    __floats2half2_rn(v2, v3);
            } else {
                float2 lo; lo.x = v0; lo.y = v1;
                float2 hi; hi.x = v2; hi.y = v3;
                *(float2*)&Cf[(long long)r * ldc + c]       = lo;
                *(float2*)&Cf[(long long)(r + 8) * ldc + c] = hi;
            }
        }
    }
}

// ---------------------------------------------------------------------------
__global__ __launch_bounds__(256)
void cvt_f2h(const float* __restrict__ in, __half* __restrict__ out, int n4)
{
    int i = blockIdx.x * blockDim.x + threadIdx.x;
    if (i < n4) {
        float4 v = ((const float4*)in)[i];
        *(__half2*)&out[i * 4]     = __floats2half2_rn(v.x, v.y);
        *(__half2*)&out[i * 4 + 2] = __floats2half2_rn(v.z, v.w);
    }
}

__global__ void pack_bias(const float* __restrict__ b0,
                          const float* __restrict__ b1,
                          const float* __restrict__ b2,
                          float* __restrict__ out)
{
    int i = threadIdx.x + blockIdx.x * blockDim.x;
    if (i < DIM) {
        out[i]           = b0[i];
        out[i + DIM]     = b1[i];
        out[i + 2 * DIM] = b2[i];
    }
}

// ---------------------------------------------------------------------------
// Transpose 3 weight matrices fp32 -> half in one launch (z selects W)
// ---------------------------------------------------------------------------
__global__ __launch_bounds__(256)
void transpose_w3(const float* __restrict__ w0, const float* __restrict__ w1,
                  const float* __restrict__ w2, __half* __restrict__ out)
{
    __shared__ float tile[32][33];
    const float* in = (blockIdx.z == 0) ? w0 : (blockIdx.z == 1) ? w1 : w2;
    __half* o = out + (size_t)blockIdx.z * DIM * DIM;
    int c = blockIdx.x * 32 + threadIdx.x;
    int r = blockIdx.y * 32 + threadIdx.y;
#pragma unroll
    for (int j = 0; j < 32; j += 8)
        tile[threadIdx.y + j][threadIdx.x] = in[(long long)(r + j) * DIM + c];
    __syncthreads();
    int c2 = blockIdx.y * 32 + threadIdx.x;
    int r2 = blockIdx.x * 32 + threadIdx.y;
#pragma unroll
    for (int j = 0; j < 32; j += 8)
        o[(long long)(r2 + j) * DIM + c2] =
            __float2half_rn(tile[threadIdx.x][threadIdx.y + j]);
}

// ---------------------------------------------------------------------------
// Transpose half -> half: out[c][r] = in[r][c]
// ---------------------------------------------------------------------------
__global__ __launch_bounds__(256)
void transpose_h2h(const __half* __restrict__ in, __half* __restrict__ out,
                   int rows, int cols)
{
    __shared__ __half tile[32][34];
    const long long zoff = (long long)blockIdx.z * rows * cols;
    int c = blockIdx.x * 32 + threadIdx.x;
    int r = blockIdx.y * 32 + threadIdx.y;
#pragma unroll
    for (int j = 0; j < 32; j += 8)
        tile[threadIdx.y + j][threadIdx.x] = in[zoff + (long long)(r + j) * cols + c];
    __syncthreads();
    int c2 = blockIdx.y * 32 + threadIdx.x;
    int r2 = blockIdx.x * 32 + threadIdx.y;
#pragma unroll
    for (int j = 0; j < 32; j += 8)
        out[zoff + (long long)(r2 + j) * rows + c2] = tile[threadIdx.x][threadIdx.y + j];
}

// ---------------------------------------------------------------------------
// Row softmax: fp32 scores in, half probs out
// ---------------------------------------------------------------------------
__global__ __launch_bounds__(256)
void softmax_rows(const float* __restrict__ Sbuf, __half* __restrict__ Pbuf)
{
    const float* p = Sbuf + (size_t)blockIdx.x * SEQ;
    __half* q = Pbuf + (size_t)blockIdx.x * SEQ;
    const int tid = threadIdx.x;

    float v[8];
    *(float4*)&v[0] = *(const float4*)&p[tid * 8 + 0];
    *(float4*)&v[4] = *(const float4*)&p[tid * 8 + 4];

    float mx = -1e30f;
#pragma unroll
    for (int i = 0; i < 8; i++) mx = fmaxf(mx, v[i]);

    __shared__ float red[8];
    __shared__ float bcast;
#pragma unroll
    for (int o = 16; o > 0; o >>= 1)
        mx = fmaxf(mx, __shfl_xor_sync(0xffffffffu, mx, o));
    if ((tid & 31) == 0) red[tid >> 5] = mx;
    __syncthreads();
    if (tid < 32) {
        float m = (tid < 8) ? red[tid] : -1e30f;
#pragma unroll
        for (int o = 4; o > 0; o >>= 1)
            m = fmaxf(m, __shfl_xor_sync(0xffffffffu, m, o));
        if (tid == 0) bcast = m;
    }
    __syncthreads();
    mx = bcast;
    __syncthreads();

    float sum = 0.f;
#pragma unroll
    for (int i = 0; i < 8; i++) { v[i] = __expf(v[i] - mx); sum += v[i]; }

#pragma unroll
    for (int o = 16; o > 0; o >>= 1)
        sum += __shfl_xor_sync(0xffffffffu, sum, o);
    if ((tid & 31) == 0) red[tid >> 5] = sum;
    __syncthreads();
    if (tid < 32) {
        float s = (tid < 8) ? red[tid] : 0.f;
#pragma unroll
        for (int o = 4; o > 0; o >>= 1)
            s += __shfl_xor_sync(0xffffffffu, s, o);
        if (tid == 0) bcast = s;
    }
    __syncthreads();
    float inv = 1.0f / bcast;

#pragma unroll
    for (int i = 0; i < 4; i++) {
        __half2 h = __floats2half2_rn(v[2 * i] * inv, v[2 * i + 1] * inv);
        *(__half2*)&q[tid * 8 + 2 * i] = h;
    }
}

// ---------------------------------------------------------------------------
extern "C" void kernel_launch(void* const* d_in, const int* in_sizes, int n_in,
                              void* d_out, int out_size)
{
    const float* X  = (const float*)d_in[0];
    const float* Wq = (const float*)d_in[1];
    const float* bq = (const float*)d_in[2];
    const float* Wk = (const float*)d_in[3];
    const float* bk = (const float*)d_in[4];
    const float* Wv = (const float*)d_in[5];
    const float* bv = (const float*)d_in[6];
    float* out = (float*)d_out;

    __half *Xh, *QKV, *Vt, *Wt, *P;
    float  *b3, *Sc;
    cudaGetSymbolAddress((void**)&Xh,  g_Xh);
    cudaGetSymbolAddress((void**)&QKV, g_QKV);
    cudaGetSymbolAddress((void**)&Vt,  g_Vt);
    cudaGetSymbolAddress((void**)&Wt,  g_Wt);
    cudaGetSymbolAddress((void**)&b3,  g_b3);
    cudaGetSymbolAddress((void**)&Sc,  g_S);
    cudaGetSymbolAddress((void**)&P,   g_P);

    const float scale = 1.0f / sqrtf((float)DIM);
    const long long QKVs = (long long)BATCH * SEQ * DIM;
    const int SMEM = 3 * ST_B;   // 165888 B

    static bool attr_set = false;
    if (!attr_set) {
        cudaFuncSetAttribute(h16gemm<true, false, true>,
                             cudaFuncAttributeMaxDynamicSharedMemorySize, SMEM);
        cudaFuncSetAttribute(h16gemm<false, true, false>,
                             cudaFuncAttributeMaxDynamicSharedMemorySize, SMEM);
        cudaFuncSetAttribute(h16gemm<false, false, false>,
                             cudaFuncAttributeMaxDynamicSharedMemorySize, SMEM);
        attr_set = true;
    }

    // 0) X -> half; W transpose+convert (one launch); pack biases
    {
        int n4 = BATCH * SEQ * DIM / 4;
        cvt_f2h<<<(n4 + 255) / 256, 256>>>(X, Xh, n4);

        dim3 tgrid(DIM / 32, DIM / 32, 3);
        dim3 tblk(32, 8, 1);
        transpose_w3<<<tgrid, tblk>>>(Wq, Wk, Wv, Wt);
        pack_bias<<<2, 256>>>(bq, bk, bv, b3);
    }

    // 1) Fused QKV projections (half out): z in {0,1,2}
    {
        dim3 grid(DIM / 256, (BATCH * SEQ) / 128, 3);
        h16gemm<true, false, true><<<grid, 256, SMEM>>>(
            BATCH * SEQ, DIM, DIM,
            Xh, DIM, 0,
            Wt, DIM, (long long)DIM * DIM,
            QKV, DIM, QKVs,
            1.0f, b3, DIM);
    }

    // 2) V transpose per batch: V[b][t][d] -> Vt[b][d][t]
    {
        dim3 tgrid(DIM / 32, SEQ / 32, BATCH);
        dim3 tblk(32, 8, 1);
        transpose_h2h<<<tgrid, tblk>>>(QKV + 2 * QKVs, Vt, SEQ, DIM);
    }

    // 3) scores = Q @ K^T * 1/sqrt(d)  (fp32 out)
    {
        dim3 grid(SEQ / 256, SEQ / 128, BATCH);
        h16gemm<false, true, false><<<grid, 256, SMEM>>>(
            SEQ, SEQ, DIM,
            QKV, DIM, (long long)SEQ * DIM,
            QKV + QKVs, DIM, (long long)SEQ * DIM,
            Sc, SEQ, (long long)SEQ * SEQ,
            scale, nullptr, 0);
    }

    // 4) row softmax: fp32 scores -> half probs
    softmax_rows<<<BATCH * SEQ, 256>>>(Sc, P);

    // 5) out = P @ V  (B = Vt[b][d][t] = [N][K]; fp32 out)
    {
        dim3 grid(DIM / 256, SEQ / 128, BATCH);
        h16gemm<false, false, false><<<grid, 256, SMEM>>>(
            SEQ, DIM, SEQ,
            P, SEQ, (long long)SEQ * SEQ,
            Vt, SEQ, (long long)SEQ * DIM,
            out, DIM, (long long)SEQ * DIM,
            1.0f, nullptr, 0);
    }
}

// round 8
// speedup vs baseline: 2.0207x; 1.0582x over previous
#include <cuda_runtime.h>
#include <cuda_fp16.h>
#include <math.h>
#include <stdint.h>

#define BATCH 4
#define SEQ   2048
#define DIM   512

// Scratch (__device__ globals — allocation-free per harness rules)
__device__ __half g_Xh [BATCH * SEQ * DIM];            // 8 MB   X in half
__device__ __half g_QKV[3 * BATCH * SEQ * DIM];        // 24 MB  Q,K,V half
__device__ __half g_Vt [BATCH * SEQ * DIM];            // 8 MB   V^T half [b][d][t]
__device__ __half g_Wt [3 * DIM * DIM];                // 1.5 MB W^T half packed
__device__ float  g_b3 [3 * DIM];                      // biases packed fp32
__device__ float  g_S  [(size_t)BATCH * SEQ * SEQ];    // 64 MB  scores fp32
__device__ __half g_P  [(size_t)BATCH * SEQ * SEQ];    // 32 MB  probs half

// ---------------------------------------------------------------------------
__device__ __forceinline__ void cpa16(__half* dst, const __half* src)
{
    uint32_t d = (uint32_t)__cvta_generic_to_shared(dst);
    asm volatile("cp.async.cg.shared.global [%0], [%1], 16;" :: "r"(d), "l"(src));
}

__device__ __forceinline__ void ldm_x4(uint32_t& r0, uint32_t& r1,
                                       uint32_t& r2, uint32_t& r3, uint32_t a)
{
    asm volatile("ldmatrix.sync.aligned.m8n8.x4.shared.b16 {%0,%1,%2,%3}, [%4];"
                 : "=r"(r0), "=r"(r1), "=r"(r2), "=r"(r3) : "r"(a));
}

// ---------------------------------------------------------------------------
// 3-stage pipelined FP16 mma.sync GEMM, 2 CTAs/SM.
// C = alpha * A[MxK] @ B[NxK]^T (+bias). A,B half row-major.
// Block tile 128x128, k-tile 64 halves (128 B rows, pitch 72 halves).
// 8 warps (2 M x 4 N), warp tile 64x32, mma m16n8k16 (fp32 accum), ldmatrix.
// smem: 3 stages x (128+128) x 72 halves = 110592 B -> 2 CTAs/SM.
// ---------------------------------------------------------------------------
#define AH    9216     // halves in A part of a stage (128*72)
#define ST_H  18432    // halves per stage ((128+128)*72)
#define ST_B  36864    // bytes per stage

template <bool HAS_BIAS, bool HAS_SCALE, bool OUT_HALF>
__global__ __launch_bounds__(256, 2)
void h16gemm(int M, int N, int K,
             const __half* __restrict__ A, int lda, long long sA,
             const __half* __restrict__ B, int ldb, long long sB,
             void* __restrict__ Cv, int ldc, long long sC,
             float alpha, const float* __restrict__ bias, long long sBias)
{
    extern __shared__ __half smh[];

    A += (long long)blockIdx.z * sA;
    B += (long long)blockIdx.z * sB;
    if (HAS_BIAS) bias += (long long)blockIdx.z * sBias;

    const int tid    = threadIdx.x;
    const int wid    = tid >> 5;
    const int lane   = tid & 31;
    const int gID    = lane >> 2;   // 0..7
    const int tig    = lane & 3;    // 0..3
    const int warp_m = wid & 1;     // 2 warps along M (64 each)
    const int warp_n = wid >> 1;    // 4 warps along N (32 each)

    const int bm = blockIdx.y * 128;
    const int bn = blockIdx.x * 128;

    // cp.async mapping: 16B chunks (8 halves). A: 1024 chunks -> 4/thread;
    // B: 1024 -> 4/thread.
    const int lrow = tid >> 3;        // 0..31 (+32*i)
    const int lc8  = (tid & 7) * 8;   // half offset within 64-half k-row

    const __half* Ap = A + (long long)(bm + lrow) * lda + lc8;
    const __half* Bp = B + (long long)(bn + lrow) * ldb + lc8;
    const int soff = lrow * 72 + lc8;   // + i*2304 (=32*72)

    // ldmatrix per-lane base addresses (bytes, shared space)
    const uint32_t sb0 = (uint32_t)__cvta_generic_to_shared(smh);
    const int l7  = lane & 7;
    const int l8  = (lane >> 3) & 1;
    const int l16 = (lane >> 4) & 1;
    // A fragments: matrices (row lo,k lo)(row hi,k lo)(row lo,k hi)(row hi,k hi)
    const uint32_t aAddr = sb0 +
        (uint32_t)(((warp_m * 64 + l7 + l8 * 8) * 72) + l16 * 8) * 2;
    // B fragments: matrices (n lo,k lo)(n lo,k hi)(n hi,k lo)(n hi,k hi)
    const uint32_t bAddr = sb0 + AH * 2 +
        (uint32_t)(((warp_n * 32 + l7 + l16 * 8) * 72) + l8 * 8) * 2;

    const int T = K >> 6;   // 64 halves per k-tile

#define ISSUE_STAGE(s, k0)                                                  \
    do {                                                                    \
        __half* sa_ = smh + (s) * ST_H;                                     \
        __half* sb_ = sa_ + AH;                                             \
        _Pragma("unroll")                                                   \
        for (int i_ = 0; i_ < 4; i_++)                                      \
            cpa16(sa_ + soff + i_ * 2304,                                   \
                  Ap + (k0) + (long long)i_ * 32 * lda);                    \
        _Pragma("unroll")                                                   \
        for (int i_ = 0; i_ < 4; i_++)                                      \
            cpa16(sb_ + soff + i_ * 2304,                                   \
                  Bp + (k0) + (long long)i_ * 32 * ldb);                    \
    } while (0)

    ISSUE_STAGE(0, 0);
    asm volatile("cp.async.commit_group;");
    if (T > 1) ISSUE_STAGE(1, 64);
    asm volatile("cp.async.commit_group;");

    float acc[4][4][4];
#pragma unroll
    for (int mi = 0; mi < 4; mi++)
#pragma unroll
        for (int ni = 0; ni < 4; ni++)
#pragma unroll
            for (int t = 0; t < 4; t++) acc[mi][ni][t] = 0.f;

    asm volatile("cp.async.wait_group 1;");
    __syncthreads();

    int s = 0;
    for (int t = 0; t < T; t++) {
        const uint32_t aS = aAddr + s * ST_B;
        const uint32_t bS = bAddr + s * ST_B;

#pragma unroll
        for (int kq = 0; kq < 4; kq++) {      // 4 k16-steps per 64-half tile
            const uint32_t ko = kq * 32;      // bytes (16 halves)
            uint32_t af[4][4], bf[4][2];
#pragma unroll
            for (int mi = 0; mi < 4; mi++)
                ldm_x4(af[mi][0], af[mi][1], af[mi][2], af[mi][3],
                       aS + mi * 2304 + ko);
#pragma unroll
            for (int np = 0; np < 2; np++)
                ldm_x4(bf[2 * np][0], bf[2 * np][1],
                       bf[2 * np + 1][0], bf[2 * np + 1][1],
                       bS + np * 2304 + ko);

            if (kq == 2) {
                if (t + 2 < T) {
                    int s2 = s + 2; if (s2 >= 3) s2 -= 3;
                    ISSUE_STAGE(s2, (t + 2) * 64);
                }
                asm volatile("cp.async.commit_group;");
            }

#pragma unroll
            for (int mi = 0; mi < 4; mi++)
#pragma unroll
                for (int ni = 0; ni < 4; ni++) {
                    asm volatile(
                        "mma.sync.aligned.m16n8k16.row.col.f32.f16.f16.f32 "
                        "{%0,%1,%2,%3}, {%4,%5,%6,%7}, {%8,%9}, {%0,%1,%2,%3};\n"
                        : "+f"(acc[mi][ni][0]), "+f"(acc[mi][ni][1]),
                          "+f"(acc[mi][ni][2]), "+f"(acc[mi][ni][3])
                        : "r"(af[mi][0]), "r"(af[mi][1]),
                          "r"(af[mi][2]), "r"(af[mi][3]),
                          "r"(bf[ni][0]), "r"(bf[ni][1]));
                }
        }

        asm volatile("cp.async.wait_group 1;");
        __syncthreads();
        if (++s == 3) s = 0;
    }
#undef ISSUE_STAGE

    // Epilogue
    __half* Ch = (__half*)Cv + (OUT_HALF ? (long long)blockIdx.z * sC : 0);
    float*  Cf = (float*)Cv  + (OUT_HALF ? 0 : (long long)blockIdx.z * sC);

#pragma unroll
    for (int mi = 0; mi < 4; mi++) {
        int r = bm + warp_m * 64 + mi * 16 + gID;
#pragma unroll
        for (int ni = 0; ni < 4; ni++) {
            int c = bn + warp_n * 32 + ni * 8 + tig * 2;
            float v0 = acc[mi][ni][0], v1 = acc[mi][ni][1];
            float v2 = acc[mi][ni][2], v3 = acc[mi][ni][3];
            if (HAS_SCALE) { v0 *= alpha; v1 *= alpha; v2 *= alpha; v3 *= alpha; }
            if (HAS_BIAS) {
                float b0 = bias[c], b1 = bias[c + 1];
                v0 += b0; v1 += b1; v2 += b0; v3 += b1;
            }
            if (OUT_HALF) {
                *(__half2*)&Ch[(long long)r * ldc + c] =
                    __floats2half2_rn(v0, v1);
                *(__half2*)&Ch[(long long)(r + 8) * ldc + c] =
                    __floats2half2_rn(v2, v3);
            } else {
                float2 lo; lo.x = v0; lo.y = v1;
                float2 hi; hi.x = v2; hi.y = v3;
                *(float2*)&Cf[(long long)r * ldc + c]       = lo;
                *(float2*)&Cf[(long long)(r + 8) * ldc + c] = hi;
            }
        }
    }
}

// ---------------------------------------------------------------------------
__global__ __launch_bounds__(256)
void cvt_f2h(const float* __restrict__ in, __half* __restrict__ out, int n4)
{
    int i = blockIdx.x * blockDim.x + threadIdx.x;
    if (i < n4) {
        float4 v = ((const float4*)in)[i];
        *(__half2*)&out[i * 4]     = __floats2half2_rn(v.x, v.y);
        *(__half2*)&out[i * 4 + 2] = __floats2half2_rn(v.z, v.w);
    }
}

__global__ void pack_bias(const float* __restrict__ b0,
                          const float* __restrict__ b1,
                          const float* __restrict__ b2,
                          float* __restrict__ out)
{
    int i = threadIdx.x + blockIdx.x * blockDim.x;
    if (i < DIM) {
        out[i]           = b0[i];
        out[i + DIM]     = b1[i];
        out[i + 2 * DIM] = b2[i];
    }
}

// ---------------------------------------------------------------------------
// Transpose 3 weight matrices fp32 -> half in one launch (z selects W)
// ---------------------------------------------------------------------------
__global__ __launch_bounds__(256)
void transpose_w3(const float* __restrict__ w0, const float* __restrict__ w1,
                  const float* __restrict__ w2, __half* __restrict__ out)
{
    __shared__ float tile[32][33];
    const float* in = (blockIdx.z == 0) ? w0 : (blockIdx.z == 1) ? w1 : w2;
    __half* o = out + (size_t)blockIdx.z * DIM * DIM;
    int c = blockIdx.x * 32 + threadIdx.x;
    int r = blockIdx.y * 32 + threadIdx.y;
#pragma unroll
    for (int j = 0; j < 32; j += 8)
        tile[threadIdx.y + j][threadIdx.x] = in[(long long)(r + j) * DIM + c];
    __syncthreads();
    int c2 = blockIdx.y * 32 + threadIdx.x;
    int r2 = blockIdx.x * 32 + threadIdx.y;
#pragma unroll
    for (int j = 0; j < 32; j += 8)
        o[(long long)(r2 + j) * DIM + c2] =
            __float2half_rn(tile[threadIdx.x][threadIdx.y + j]);
}

// ---------------------------------------------------------------------------
// Transpose half -> half: out[c][r] = in[r][c]
// ---------------------------------------------------------------------------
__global__ __launch_bounds__(256)
void transpose_h2h(const __half* __restrict__ in, __half* __restrict__ out,
                   int rows, int cols)
{
    __shared__ __half tile[32][34];
    const long long zoff = (long long)blockIdx.z * rows * cols;
    int c = blockIdx.x * 32 + threadIdx.x;
    int r = blockIdx.y * 32 + threadIdx.y;
#pragma unroll
    for (int j = 0; j < 32; j += 8)
        tile[threadIdx.y + j][threadIdx.x] = in[zoff + (long long)(r + j) * cols + c];
    __syncthreads();
    int c2 = blockIdx.y * 32 + threadIdx.x;
    int r2 = blockIdx.x * 32 + threadIdx.y;
#pragma unroll
    for (int j = 0; j < 32; j += 8)
        out[zoff + (long long)(r2 + j) * rows + c2] = tile[threadIdx.x][threadIdx.y + j];
}

// ---------------------------------------------------------------------------
// Row softmax: fp32 scores in, half probs out
// ---------------------------------------------------------------------------
__global__ __launch_bounds__(256)
void softmax_rows(const float* __restrict__ Sbuf, __half* __restrict__ Pbuf)
{
    const float* p = Sbuf + (size_t)blockIdx.x * SEQ;
    __half* q = Pbuf + (size_t)blockIdx.x * SEQ;
    const int tid = threadIdx.x;

    float v[8];
    *(float4*)&v[0] = *(const float4*)&p[tid * 8 + 0];
    *(float4*)&v[4] = *(const float4*)&p[tid * 8 + 4];

    float mx = -1e30f;
#pragma unroll
    for (int i = 0; i < 8; i++) mx = fmaxf(mx, v[i]);

    __shared__ float red[8];
    __shared__ float bcast;
#pragma unroll
    for (int o = 16; o > 0; o >>= 1)
        mx = fmaxf(mx, __shfl_xor_sync(0xffffffffu, mx, o));
    if ((tid & 31) == 0) red[tid >> 5] = mx;
    __syncthreads();
    if (tid < 32) {
        float m = (tid < 8) ? red[tid] : -1e30f;
#pragma unroll
        for (int o = 4; o > 0; o >>= 1)
            m = fmaxf(m, __shfl_xor_sync(0xffffffffu, m, o));
        if (tid == 0) bcast = m;
    }
    __syncthreads();
    mx = bcast;
    __syncthreads();

    float sum = 0.f;
#pragma unroll
    for (int i = 0; i < 8; i++) { v[i] = __expf(v[i] - mx); sum += v[i]; }

#pragma unroll
    for (int o = 16; o > 0; o >>= 1)
        sum += __shfl_xor_sync(0xffffffffu, sum, o);
    if ((tid & 31) == 0) red[tid >> 5] = sum;
    __syncthreads();
    if (tid < 32) {
        float s = (tid < 8) ? red[tid] : 0.f;
#pragma unroll
        for (int o = 4; o > 0; o >>= 1)
            s += __shfl_xor_sync(0xffffffffu, s, o);
        if (tid == 0) bcast = s;
    }
    __syncthreads();
    float inv = 1.0f / bcast;

#pragma unroll
    for (int i = 0; i < 4; i++) {
        __half2 h = __floats2half2_rn(v[2 * i] * inv, v[2 * i + 1] * inv);
        *(__half2*)&q[tid * 8 + 2 * i] = h;
    }
}

// ---------------------------------------------------------------------------
extern "C" void kernel_launch(void* const* d_in, const int* in_sizes, int n_in,
                              void* d_out, int out_size)
{
    const float* X  = (const float*)d_in[0];
    const float* Wq = (const float*)d_in[1];
    const float* bq = (const float*)d_in[2];
    const float* Wk = (const float*)d_in[3];
    const float* bk = (const float*)d_in[4];
    const float* Wv = (const float*)d_in[5];
    const float* bv = (const float*)d_in[6];
    float* out = (float*)d_out;

    __half *Xh, *QKV, *Vt, *Wt, *P;
    float  *b3, *Sc;
    cudaGetSymbolAddress((void**)&Xh,  g_Xh);
    cudaGetSymbolAddress((void**)&QKV, g_QKV);
    cudaGetSymbolAddress((void**)&Vt,  g_Vt);
    cudaGetSymbolAddress((void**)&Wt,  g_Wt);
    cudaGetSymbolAddress((void**)&b3,  g_b3);
    cudaGetSymbolAddress((void**)&Sc,  g_S);
    cudaGetSymbolAddress((void**)&P,   g_P);

    const float scale = 1.0f / sqrtf((float)DIM);
    const long long QKVs = (long long)BATCH * SEQ * DIM;
    const int SMEM = 3 * ST_B;   // 110592 B

    cudaFuncSetAttribute(h16gemm<true, false, true>,
                         cudaFuncAttributeMaxDynamicSharedMemorySize, SMEM);
    cudaFuncSetAttribute(h16gemm<false, true, false>,
                         cudaFuncAttributeMaxDynamicSharedMemorySize, SMEM);
    cudaFuncSetAttribute(h16gemm<false, false, false>,
                         cudaFuncAttributeMaxDynamicSharedMemorySize, SMEM);

    // 0) X -> half; W transpose+convert (one launch); pack biases
    {
        int n4 = BATCH * SEQ * DIM / 4;
        cvt_f2h<<<(n4 + 255) / 256, 256>>>(X, Xh, n4);

        dim3 tgrid(DIM / 32, DIM / 32, 3);
        dim3 tblk(32, 8, 1);
        transpose_w3<<<tgrid, tblk>>>(Wq, Wk, Wv, Wt);
        pack_bias<<<2, 256>>>(bq, bk, bv, b3);
    }

    // 1) Fused QKV projections (half out): z in {0,1,2}
    {
        dim3 grid(DIM / 128, (BATCH * SEQ) / 128, 3);
        h16gemm<true, false, true><<<grid, 256, SMEM>>>(
            BATCH * SEQ, DIM, DIM,
            Xh, DIM, 0,
            Wt, DIM, (long long)DIM * DIM,
            QKV, DIM, QKVs,
            1.0f, b3, DIM);
    }

    // 2) V transpose per batch: V[b][t][d] -> Vt[b][d][t]
    {
        dim3 tgrid(DIM / 32, SEQ / 32, BATCH);
        dim3 tblk(32, 8, 1);
        transpose_h2h<<<tgrid, tblk>>>(QKV + 2 * QKVs, Vt, SEQ, DIM);
    }

    // 3) scores = Q @ K^T * 1/sqrt(d)  (fp32 out)
    {
        dim3 grid(SEQ / 128, SEQ / 128, BATCH);
        h16gemm<false, true, false><<<grid, 256, SMEM>>>(
            SEQ, SEQ, DIM,
            QKV, DIM, (long long)SEQ * DIM,
            QKV + QKVs, DIM, (long long)SEQ * DIM,
            Sc, SEQ, (long long)SEQ * SEQ,
            scale, nullptr, 0);
    }

    // 4) row softmax: fp32 scores -> half probs
    softmax_rows<<<BATCH * SEQ, 256>>>(Sc, P);

    // 5) out = P @ V  (B = Vt[b][d][t] = [N][K]; fp32 out)
    {
        dim3 grid(DIM / 128, SEQ / 128, BATCH);
        h16gemm<false, false, false><<<grid, 256, SMEM>>>(
            SEQ, DIM, SEQ,
            P, SEQ, (long long)SEQ * SEQ,
            Vt, SEQ, (long long)SEQ * DIM,
            out, DIM, (long long)SEQ * DIM,
            1.0f, nullptr, 0);
    }
}